// round 16
// baseline (speedup 1.0000x reference)
#include <cuda_runtime.h>
#include <cuda_bf16.h>
#include <math.h>
#include <stdint.h>

#define NTOK 2048   // B*N
#define DMODEL 1024
#define NSEQ 1024
#define NB 2
#define NH 16
#define HD 64

// Output layout (float32, concatenated in reference return order)
#define OFF_FIN 0
#define OFF_FWD 2097152
#define OFF_BWD 2099200
#define OFF_STR 2101248

// scratch (device globals — no runtime allocation allowed)
__device__ float g_HF[NTOK * DMODEL];                     // head_features (tf32-rounded)
__device__ float g_cp[32][DMODEL];                        // per (m-tile, warp-row) colsums
__device__ alignas(16) float g_hT[NTOK * DMODEL];         // h, tf32-rounded
__device__ alignas(16) float g_WvT[DMODEL * DMODEL];      // Wv, tf32-rounded
__device__ alignas(16) float g_WoT[DMODEL * DMODEL];      // Wo, tf32-rounded
__device__ alignas(16) float g_multiT[NTOK * DMODEL];     // multi, tf32-rounded
__device__ alignas(16) float g_W1aT[NH * HD * HD];        // fuW1[:, :, 0:64], tf32
__device__ alignas(16) float g_W2T[NH * HD * HD];         // fuW2, tf32

// ---------------------------------------------------------------------------
// fp32 -> tf32 (RN) converts, all tensors in one launch
// ---------------------------------------------------------------------------
__device__ __forceinline__ float tf32r(float x) {
    uint32_t r;
    asm("cvt.rn.tf32.f32 %0, %1;" : "=r"(r) : "f"(x));
    return __uint_as_float(r);
}

__device__ __forceinline__ void cvt4(const float* __restrict__ in,
                                     float* __restrict__ out, int i) {
    float4 v = *(const float4*)(in + i);
    v.x = tf32r(v.x); v.y = tf32r(v.y); v.z = tf32r(v.z); v.w = tf32r(v.w);
    *(float4*)(out + i) = v;
}

__global__ void tf32_all(const float* __restrict__ h,
                         const float* __restrict__ Wv,
                         const float* __restrict__ Wo,
                         const float* __restrict__ fuW1,
                         const float* __restrict__ fuW2)
{
    int id = blockIdx.x * blockDim.x + threadIdx.x;
    if (id < 524288) {
        cvt4(h,  g_hT,  id * 4);
    } else if (id < 786432) {
        cvt4(Wv, g_WvT, (id - 524288) * 4);
    } else if (id < 1048576) {
        cvt4(Wo, g_WoT, (id - 786432) * 4);
    } else if (id < 1064960) {
        int i = (id - 1048576) * 4;      // over 16*64*64 = 65536 elems
        int row = i >> 6, e = i & 63;    // row = h*64+j
        float4 v = *(const float4*)(fuW1 + (size_t)row * (3 * HD) + e);
        v.x = tf32r(v.x); v.y = tf32r(v.y); v.z = tf32r(v.z); v.w = tf32r(v.w);
        *(float4*)(g_W1aT + i) = v;
    } else if (id < 1081344) {
        cvt4(fuW2, g_W2T, (id - 1064960) * 4);   // fuW2 rows are contiguous 64
    }
}

// ---------------------------------------------------------------------------
// tf32 mma.sync NT GEMM: C[m][n] = sum_k A[m][k]*W[n][k], fp32 accum. K=1024.
// CTA 128x64, 4 warps (2x2), warp tile 64x32, mma m16n8k8.
// do_colsum: fused colsums into g_cp AND tf32-round the C output (HF path).
// ---------------------------------------------------------------------------
#define TILE_M 128
#define TILE_N 64
#define GBK 32                         // floats per chunk (128B rows)
#define NCH (DMODEL / GBK)             // 32
#define NSTG 3
#define AREG_B (TILE_M * 128)          // 16384 bytes
#define BREG_B (TILE_N * 128)          //  8192 bytes
#define STG_BYTES (AREG_B + BREG_B)    // 24576
#define GEMM_SMEM (NSTG * STG_BYTES)   // 73728

__device__ __forceinline__ void cp16(uint32_t s, const void* g) {
    asm volatile("cp.async.cg.shared.global [%0], [%1], 16;\n" :: "r"(s), "l"(g));
}

__global__ __launch_bounds__(128) void gemm_tf32_nt(
    const float* __restrict__ A, const float* __restrict__ W,
    float* __restrict__ C, int Nn, int do_colsum)
{
    extern __shared__ char dsm[];
    const int tid = threadIdx.x;
    const int lane = tid & 31;
    const int w = tid >> 5;
    const int m0 = blockIdx.y * TILE_M;
    const int n0 = blockIdx.x * TILE_N;
    const int wm = (w >> 1) * 64;
    const int wn = (w & 1) * 32;

    const uint32_t sBase = (uint32_t)__cvta_generic_to_shared(dsm);

    const int a_row = wm + (lane & 7) + ((lane >> 3) & 1) * 8;
    const int a_c4 = (lane >> 4) & 1;
    const int b_row = wn + (lane & 7) + ((lane >> 4) & 1) * 8;
    const int b_c4 = (lane >> 3) & 1;

    float acc[4][4][4];
#pragma unroll
    for (int i = 0; i < 4; ++i)
#pragma unroll
        for (int j = 0; j < 4; ++j)
#pragma unroll
            for (int r = 0; r < 4; ++r) acc[i][j][r] = 0.0f;

    auto load_chunk = [&](int ck) {
        int stg = ck % NSTG;
        uint32_t sa = sBase + stg * STG_BYTES;
        uint32_t sb = sa + AREG_B;
        int k0 = ck * GBK;
#pragma unroll
        for (int j = 0; j < 8; ++j) {
            int c = tid + j * 128;
            int r = c >> 3;
            int ci = c & 7;
            cp16(sa + r * 128 + ((ci ^ (r & 7)) << 4),
                 A + (size_t)(m0 + r) * DMODEL + k0 + ci * 4);
        }
#pragma unroll
        for (int j = 0; j < 4; ++j) {
            int c = tid + j * 128;
            int r = c >> 3;
            int ci = c & 7;
            cp16(sb + r * 128 + ((ci ^ (r & 7)) << 4),
                 W + (size_t)(n0 + r) * DMODEL + k0 + ci * 4);
        }
        asm volatile("cp.async.commit_group;\n");
    };

    load_chunk(0);
    load_chunk(1);

    for (int it = 0; it < NCH; ++it) {
        if (it < NCH - 1) asm volatile("cp.async.wait_group 1;\n");
        else              asm volatile("cp.async.wait_group 0;\n");
        __syncthreads();
        if (it + 2 < NCH) load_chunk(it + 2);

        const uint32_t sa = sBase + (it % NSTG) * STG_BYTES;
        const uint32_t sb = sa + AREG_B;

        uint32_t af[2][4][4];
        uint32_t bf[2][4][2];

        auto ldfrag = [&](int buf, int ks) {
#pragma unroll
            for (int mi = 0; mi < 4; ++mi) {
                int r = a_row + mi * 16;
                int ci = ks * 2 + a_c4;
                uint32_t addr = sa + r * 128 + ((ci ^ (r & 7)) << 4);
                asm volatile(
                    "ldmatrix.sync.aligned.m8n8.x4.shared.b16 {%0,%1,%2,%3},[%4];\n"
                    : "=r"(af[buf][mi][0]), "=r"(af[buf][mi][1]),
                      "=r"(af[buf][mi][2]), "=r"(af[buf][mi][3])
                    : "r"(addr));
            }
#pragma unroll
            for (int np = 0; np < 2; ++np) {
                int r = b_row + np * 16;
                int ci = ks * 2 + b_c4;
                uint32_t addr = sb + r * 128 + ((ci ^ (r & 7)) << 4);
                uint32_t r0, r1, r2, r3;
                asm volatile(
                    "ldmatrix.sync.aligned.m8n8.x4.shared.b16 {%0,%1,%2,%3},[%4];\n"
                    : "=r"(r0), "=r"(r1), "=r"(r2), "=r"(r3) : "r"(addr));
                bf[buf][np * 2][0] = r0;     bf[buf][np * 2][1] = r1;
                bf[buf][np * 2 + 1][0] = r2; bf[buf][np * 2 + 1][1] = r3;
            }
        };

        ldfrag(0, 0);
#pragma unroll
        for (int ks = 0; ks < 4; ++ks) {
            if (ks < 3) ldfrag((ks + 1) & 1, ks + 1);
            const int cur = ks & 1;
#pragma unroll
            for (int mi = 0; mi < 4; ++mi)
#pragma unroll
                for (int ni = 0; ni < 4; ++ni) {
                    asm volatile(
                        "mma.sync.aligned.m16n8k8.row.col.f32.tf32.tf32.f32 "
                        "{%0,%1,%2,%3},{%4,%5,%6,%7},{%8,%9},{%0,%1,%2,%3};\n"
                        : "+f"(acc[mi][ni][0]), "+f"(acc[mi][ni][1]),
                          "+f"(acc[mi][ni][2]), "+f"(acc[mi][ni][3])
                        : "r"(af[cur][mi][0]), "r"(af[cur][mi][1]),
                          "r"(af[cur][mi][2]), "r"(af[cur][mi][3]),
                          "r"(bf[cur][ni][0]), "r"(bf[cur][ni][1]));
                }
        }
    }

    const int g = lane >> 2;
    const int cc = (lane & 3) * 2;
#pragma unroll
    for (int mi = 0; mi < 4; ++mi) {
#pragma unroll
        for (int ni = 0; ni < 4; ++ni) {
            int row = m0 + wm + mi * 16 + g;
            int col = n0 + wn + ni * 8 + cc;
            float v0 = acc[mi][ni][0], v1 = acc[mi][ni][1];
            float v2 = acc[mi][ni][2], v3 = acc[mi][ni][3];
            if (do_colsum) {   // HF path: pre-round for the tf32 fusion MMA
                v0 = tf32r(v0); v1 = tf32r(v1); v2 = tf32r(v2); v3 = tf32r(v3);
            }
            *(float2*)(C + (size_t)row * Nn + col) = make_float2(v0, v1);
            *(float2*)(C + (size_t)(row + 8) * Nn + col) = make_float2(v2, v3);
        }
    }

    if (do_colsum) {
        float cs[4][2];
#pragma unroll
        for (int ni = 0; ni < 4; ++ni) {
            float s0 = 0.0f, s1 = 0.0f;
#pragma unroll
            for (int mi = 0; mi < 4; ++mi) {
                s0 += acc[mi][ni][0] + acc[mi][ni][2];
                s1 += acc[mi][ni][1] + acc[mi][ni][3];
            }
            cs[ni][0] = s0;
            cs[ni][1] = s1;
        }
#pragma unroll
        for (int off = 4; off < 32; off <<= 1) {
#pragma unroll
            for (int ni = 0; ni < 4; ++ni) {
                cs[ni][0] += __shfl_xor_sync(0xffffffffu, cs[ni][0], off);
                cs[ni][1] += __shfl_xor_sync(0xffffffffu, cs[ni][1], off);
            }
        }
        if (lane < 4) {
            int slot = (m0 >> 7) * 2 + (wm >> 6);
#pragma unroll
            for (int ni = 0; ni < 4; ++ni) {
                g_cp[slot][n0 + wn + ni * 8 + lane * 2]     = cs[ni][0];
                g_cp[slot][n0 + wn + ni * 8 + lane * 2 + 1] = cs[ni][1];
            }
        }
    }
}

// ---------------------------------------------------------------------------
// Tensor-core fusion MLP. Per (128-token tile, head) block, 128 threads.
// Stage1: S = X(128x64) @ W1a^T (tf32 mma) + cvec -> exact GELU -> tf32 -> G
// Stage2: out = G @ W2^T + b2 -> tf32 -> g_multiT.
// X/G smem: 2 chunks x 16KB (128B rows, XOR swizzle). W: 2 chunks x 8KB.
// ---------------------------------------------------------------------------
#define FUS_X_OFF 0
#define FUS_W_OFF 32768
#define FUS_MN_OFF 49152
#define FUS_CV_OFF 49408
#define FUS_SMEM  49664

__device__ __forceinline__ float gelu_exact(float x) {
    return 0.5f * x * (1.0f + erff(x * 0.70710678118654752f));
}

__global__ __launch_bounds__(128) void fusion_tc(
    const float* __restrict__ fuW1, const float* __restrict__ fub1,
    const float* __restrict__ fub2)
{
    extern __shared__ char fsm[];
    const uint32_t sX = (uint32_t)__cvta_generic_to_shared(fsm) + FUS_X_OFF;
    const uint32_t sW = sX + (FUS_W_OFF - FUS_X_OFF);
    float* mnS = (float*)(fsm + FUS_MN_OFF);
    float* cvS = (float*)(fsm + FUS_CV_OFF);

    const int tid = threadIdx.x;
    const int lane = tid & 31;
    const int w = tid >> 5;
    const int m0 = blockIdx.x * 128;
    const int h = blockIdx.y;
    const int b = m0 >> 10;
    const int wm = (w >> 1) * 64;
    const int wn = (w & 1) * 32;

    const int a_row = wm + (lane & 7) + ((lane >> 3) & 1) * 8;
    const int a_c4 = (lane >> 4) & 1;
    const int b_row = wn + (lane & 7) + ((lane >> 4) & 1) * 8;
    const int b_c4 = (lane >> 3) & 1;

    // async loads: X (2048 16B chunks), W1a (1024 16B chunks)
#pragma unroll
    for (int j = 0; j < 16; ++j) {
        int c = tid + j * 128;
        int kc = c >> 10;
        int c2 = c & 1023;
        int r = c2 >> 3, ci = c2 & 7;
        cp16(sX + kc * 16384 + r * 128 + ((ci ^ (r & 7)) << 4),
             g_HF + (size_t)(m0 + r) * DMODEL + h * HD + kc * 32 + ci * 4);
    }
#pragma unroll
    for (int j = 0; j < 8; ++j) {
        int c = tid + j * 128;
        int kc = c >> 9;
        int c2 = c & 511;
        int r = c2 >> 3, ci = c2 & 7;
        cp16(sW + kc * 8192 + r * 128 + ((ci ^ (r & 7)) << 4),
             g_W1aT + (size_t)(h * HD + r) * HD + kc * 32 + ci * 4);
    }
    asm volatile("cp.async.commit_group;\n");

    // sequence mean (from gemm1's fused colsum partials)
    if (tid < HD) {
        int c = h * HD + tid;
        float s = 0.0f;
#pragma unroll
        for (int q = 0; q < 16; ++q)
            s += g_cp[b * 16 + q][c];
        mnS[tid] = s * (1.0f / 1024.0f);
    }
    __syncthreads();   // mnS visible

    // inline cvec: 2 threads per j-row (fp32, from global fuW1 mid segment)
    {
        const int j = tid >> 1;
        const int t = tid & 1;
        const float* wrow = fuW1 + (size_t)(h * HD + j) * (3 * HD);
        float cacc = 0.0f;
#pragma unroll
        for (int q = 0; q < 8; ++q) {
            int e = t * 32 + q * 4;
            float4 wa = *(const float4*)(wrow + 64 + e);
            float4 wb = *(const float4*)(wrow + 128 + e);
            cacc = fmaf(wa.x + wb.x, mnS[e + 0], cacc);
            cacc = fmaf(wa.y + wb.y, mnS[e + 1], cacc);
            cacc = fmaf(wa.z + wb.z, mnS[e + 2], cacc);
            cacc = fmaf(wa.w + wb.w, mnS[e + 3], cacc);
        }
        cacc += __shfl_down_sync(0xffffffffu, cacc, 1, 2);
        if (t == 0) cvS[j] = cacc + fub1[h * HD + j];
    }

    asm volatile("cp.async.wait_group 0;\n");
    __syncthreads();

    uint32_t af[2][4][4];
    uint32_t bf[2][4][2];

    auto ldfrag = [&](uint32_t sa, uint32_t sb, int buf, int ks) {
#pragma unroll
        for (int mi = 0; mi < 4; ++mi) {
            int r = a_row + mi * 16;
            int ci = ks * 2 + a_c4;
            uint32_t addr = sa + r * 128 + ((ci ^ (r & 7)) << 4);
            asm volatile(
                "ldmatrix.sync.aligned.m8n8.x4.shared.b16 {%0,%1,%2,%3},[%4];\n"
                : "=r"(af[buf][mi][0]), "=r"(af[buf][mi][1]),
                  "=r"(af[buf][mi][2]), "=r"(af[buf][mi][3])
                : "r"(addr));
        }
#pragma unroll
        for (int np = 0; np < 2; ++np) {
            int r = b_row + np * 16;
            int ci = ks * 2 + b_c4;
            uint32_t addr = sb + r * 128 + ((ci ^ (r & 7)) << 4);
            uint32_t r0, r1, r2, r3;
            asm volatile(
                "ldmatrix.sync.aligned.m8n8.x4.shared.b16 {%0,%1,%2,%3},[%4];\n"
                : "=r"(r0), "=r"(r1), "=r"(r2), "=r"(r3) : "r"(addr));
            bf[buf][np * 2][0] = r0;     bf[buf][np * 2][1] = r1;
            bf[buf][np * 2 + 1][0] = r2; bf[buf][np * 2 + 1][1] = r3;
        }
    };

    auto mma_stage = [&](float (&ACC)[4][4][4]) {
#pragma unroll
        for (int kc = 0; kc < 2; ++kc) {
            const uint32_t sa = sX + kc * 16384;
            const uint32_t sb = sW + kc * 8192;
            ldfrag(sa, sb, 0, 0);
#pragma unroll
            for (int ks = 0; ks < 4; ++ks) {
                if (ks < 3) ldfrag(sa, sb, (ks + 1) & 1, ks + 1);
                const int cur = ks & 1;
#pragma unroll
                for (int mi = 0; mi < 4; ++mi)
#pragma unroll
                    for (int ni = 0; ni < 4; ++ni) {
                        asm volatile(
                            "mma.sync.aligned.m16n8k8.row.col.f32.tf32.tf32.f32 "
                            "{%0,%1,%2,%3},{%4,%5,%6,%7},{%8,%9},{%0,%1,%2,%3};\n"
                            : "+f"(ACC[mi][ni][0]), "+f"(ACC[mi][ni][1]),
                              "+f"(ACC[mi][ni][2]), "+f"(ACC[mi][ni][3])
                            : "r"(af[cur][mi][0]), "r"(af[cur][mi][1]),
                              "r"(af[cur][mi][2]), "r"(af[cur][mi][3]),
                              "r"(bf[cur][ni][0]), "r"(bf[cur][ni][1]));
                    }
            }
        }
    };

    float acc[4][4][4];
#pragma unroll
    for (int i = 0; i < 4; ++i)
#pragma unroll
        for (int j = 0; j < 4; ++j)
#pragma unroll
            for (int r = 0; r < 4; ++r) acc[i][j][r] = 0.0f;

    mma_stage(acc);
    __syncthreads();   // all ldmatrix reads of X/W1 done

    // GELU(+cv) -> tf32 -> G (overwrites X buffer); load W2 async
    const int g = lane >> 2;
    const int cc = (lane & 3) * 2;
#pragma unroll
    for (int mi = 0; mi < 4; ++mi) {
#pragma unroll
        for (int ni = 0; ni < 4; ++ni) {
            int j0 = wn + ni * 8 + cc;
            float cv0 = cvS[j0], cv1 = cvS[j0 + 1];
            float x0 = tf32r(gelu_exact(acc[mi][ni][0] + cv0));
            float x1 = tf32r(gelu_exact(acc[mi][ni][1] + cv1));
            float x2 = tf32r(gelu_exact(acc[mi][ni][2] + cv0));
            float x3 = tf32r(gelu_exact(acc[mi][ni][3] + cv1));
            int kc = j0 >> 5;
            int cl = j0 & 31;
            int ci = cl >> 2;
            int r0 = wm + mi * 16 + g;
            int r1 = r0 + 8;
            uint32_t ad0 = sX + kc * 16384 + r0 * 128 +
                           ((ci ^ (r0 & 7)) << 4) + (cl & 3) * 4;
            uint32_t ad1 = sX + kc * 16384 + r1 * 128 +
                           ((ci ^ (r1 & 7)) << 4) + (cl & 3) * 4;
            asm volatile("st.shared.v2.f32 [%0], {%1,%2};"
                         :: "r"(ad0), "f"(x0), "f"(x1) : "memory");
            asm volatile("st.shared.v2.f32 [%0], {%1,%2};"
                         :: "r"(ad1), "f"(x2), "f"(x3) : "memory");
        }
    }
#pragma unroll
    for (int j = 0; j < 8; ++j) {
        int c = tid + j * 128;
        int kc = c >> 9;
        int c2 = c & 511;
        int r = c2 >> 3, ci = c2 & 7;
        cp16(sW + kc * 8192 + r * 128 + ((ci ^ (r & 7)) << 4),
             g_W2T + (size_t)(h * HD + r) * HD + kc * 32 + ci * 4);
    }
    asm volatile("cp.async.commit_group;\n");
    asm volatile("cp.async.wait_group 0;\n");
    __syncthreads();   // G + W2 visible

    float acc2[4][4][4];
#pragma unroll
    for (int i = 0; i < 4; ++i)
#pragma unroll
        for (int j = 0; j < 4; ++j)
#pragma unroll
            for (int r = 0; r < 4; ++r) acc2[i][j][r] = 0.0f;

    mma_stage(acc2);

    // epilogue: +b2, tf32 round, store multi
#pragma unroll
    for (int mi = 0; mi < 4; ++mi) {
#pragma unroll
        for (int ni = 0; ni < 4; ++ni) {
            int f0 = wn + ni * 8 + cc;
            float b0 = fub2[h * HD + f0];
            float b1 = fub2[h * HD + f0 + 1];
            int row = m0 + wm + mi * 16 + g;
            size_t base = (size_t)row * DMODEL + h * HD + f0;
            *(float2*)&g_multiT[base] =
                make_float2(tf32r(acc2[mi][ni][0] + b0),
                            tf32r(acc2[mi][ni][1] + b1));
            *(float2*)&g_multiT[base + 8 * DMODEL] =
                make_float2(tf32r(acc2[mi][ni][2] + b0),
                            tf32r(acc2[mi][ni][3] + b1));
        }
    }
}

// ---------------------------------------------------------------------------
// Trivial outputs: fwd/bwd targets + avg_strength (analytic constants)
// ---------------------------------------------------------------------------
__global__ void extras_kernel(const int* __restrict__ prev,
                              const float* __restrict__ cr,
                              float* __restrict__ out)
{
    int idx = blockIdx.x * blockDim.x + threadIdx.x;
    if (idx >= NTOK) return;
    int n = idx & (NSEQ - 1);

    float thr = floorf((float)NSEQ / (1.0f + expf(-cr[0])));
    float fwd = 511.0f;
    if ((float)n >= thr) {
        int p = prev[idx];
        p = p < 0 ? 0 : (p > NSEQ - 1 ? NSEQ - 1 : p);
        fwd = (float)p;
    }
    out[OFF_FWD + idx] = fwd;
    out[OFF_BWD + idx] = 511.0f;
    out[OFF_STR + idx] = 1.0f - logf(1.0f / (float)NSEQ + 1e-8f);
}

// ---------------------------------------------------------------------------
extern "C" void kernel_launch(void* const* d_in, const int* in_sizes, int n_in,
                              void* d_out, int out_size)
{
    const float* h    = (const float*)d_in[0];
    const int*   prev = (const int*)d_in[1];
    // d_in[2..9]: forward/backward encoder weights — provably dead code
    const float* Wv   = (const float*)d_in[10];
    const float* fuW1 = (const float*)d_in[11];
    const float* fub1 = (const float*)d_in[12];
    const float* fuW2 = (const float*)d_in[13];
    const float* fub2 = (const float*)d_in[14];
    const float* Wo   = (const float*)d_in[15];
    const float* cr   = (const float*)d_in[16];
    float* out = (float*)d_out;

    float *pHF = nullptr, *phT = nullptr, *pWvT = nullptr, *pWoT = nullptr,
          *pMT = nullptr;
    cudaGetSymbolAddress((void**)&pHF, g_HF);
    cudaGetSymbolAddress((void**)&phT, g_hT);
    cudaGetSymbolAddress((void**)&pWvT, g_WvT);
    cudaGetSymbolAddress((void**)&pWoT, g_WoT);
    cudaGetSymbolAddress((void**)&pMT, g_multiT);

    cudaFuncSetAttribute(gemm_tf32_nt,
                         cudaFuncAttributeMaxDynamicSharedMemorySize, GEMM_SMEM);
    cudaFuncSetAttribute(fusion_tc,
                         cudaFuncAttributeMaxDynamicSharedMemorySize, FUS_SMEM);

    // 0) tf32-RN converts in one launch (h, Wv, Wo, W1a, W2)
    tf32_all<<<4224, 256>>>(h, Wv, Wo, fuW1, fuW2);

    dim3 g1(DMODEL / TILE_N, NTOK / TILE_M);   // (16, 16) = 256 CTAs

    // 1) head_features = h @ Wv^T  (tf32 mma) + colsums; HF stored tf32-rounded
    gemm_tf32_nt<<<g1, 128, GEMM_SMEM>>>(phT, pWvT, pHF, DMODEL, 1);

    // 2) tensor-core fusion MLP -> g_multiT
    fusion_tc<<<dim3(NTOK / 128, NH), 128, FUS_SMEM>>>(fuW1, fub1, fub2);

    // 3) final_output = multi @ Wo^T
    gemm_tf32_nt<<<g1, 128, GEMM_SMEM>>>(pMT, pWoT, out, DMODEL, 0);

    // 4) analytic outputs
    extras_kernel<<<(NTOK + 255) / 256, 256>>>(prev, cr, out);
}

// round 17
// speedup vs baseline: 1.7031x; 1.7031x over previous
#include <cuda_runtime.h>
#include <cuda_bf16.h>
#include <math.h>
#include <stdint.h>

#define NTOK 2048   // B*N
#define DMODEL 1024
#define NSEQ 1024
#define NB 2
#define NH 16
#define HD 64

// Output layout (float32, concatenated in reference return order)
#define OFF_FIN 0
#define OFF_FWD 2097152
#define OFF_BWD 2099200
#define OFF_STR 2101248

// scratch (device globals — no runtime allocation allowed)
__device__ float g_HF[NTOK * DMODEL];                     // head_features (tf32-rounded)
__device__ float g_cp[32][DMODEL];                        // per (m-tile, warp-row) colsums
__device__ alignas(16) float g_hT[NTOK * DMODEL];         // h, tf32-rounded
__device__ alignas(16) float g_WvT[DMODEL * DMODEL];      // Wv, tf32-rounded
__device__ alignas(16) float g_WoT[DMODEL * DMODEL];      // Wo, tf32-rounded
__device__ alignas(16) float g_multiT[NTOK * DMODEL];     // multi, tf32-rounded
__device__ alignas(16) float g_W1aT[NH * HD * HD];        // fuW1[:, :, 0:64], tf32
__device__ alignas(16) float g_W2T[NH * HD * HD];         // fuW2, tf32

// ---------------------------------------------------------------------------
// fp32 -> tf32 (RN) converts, all tensors in one launch
// ---------------------------------------------------------------------------
__device__ __forceinline__ float tf32r(float x) {
    uint32_t r;
    asm("cvt.rn.tf32.f32 %0, %1;" : "=r"(r) : "f"(x));
    return __uint_as_float(r);
}

__device__ __forceinline__ void cvt4(const float* __restrict__ in,
                                     float* __restrict__ out, int i) {
    float4 v = *(const float4*)(in + i);
    v.x = tf32r(v.x); v.y = tf32r(v.y); v.z = tf32r(v.z); v.w = tf32r(v.w);
    *(float4*)(out + i) = v;
}

__global__ void tf32_all(const float* __restrict__ h,
                         const float* __restrict__ Wv,
                         const float* __restrict__ Wo,
                         const float* __restrict__ fuW1,
                         const float* __restrict__ fuW2)
{
    int id = blockIdx.x * blockDim.x + threadIdx.x;
    if (id < 524288) {
        cvt4(h,  g_hT,  id * 4);
    } else if (id < 786432) {
        cvt4(Wv, g_WvT, (id - 524288) * 4);
    } else if (id < 1048576) {
        cvt4(Wo, g_WoT, (id - 786432) * 4);
    } else if (id < 1064960) {
        int i = (id - 1048576) * 4;      // over 16*64*64 = 65536 elems
        int row = i >> 6, e = i & 63;    // row = h*64+j
        float4 v = *(const float4*)(fuW1 + (size_t)row * (3 * HD) + e);
        v.x = tf32r(v.x); v.y = tf32r(v.y); v.z = tf32r(v.z); v.w = tf32r(v.w);
        *(float4*)(g_W1aT + i) = v;
    } else if (id < 1081344) {
        cvt4(fuW2, g_W2T, (id - 1064960) * 4);   // fuW2 rows are contiguous 64
    }
}

// ---------------------------------------------------------------------------
// tf32 mma.sync NT GEMM: C[m][n] = sum_k A[m][k]*W[n][k], fp32 accum. K=1024.
// CTA 128x64, 4 warps (2x2), warp tile 64x32, mma m16n8k8.
// do_colsum: fused colsums into g_cp AND tf32-round the C output (HF path).
// ---------------------------------------------------------------------------
#define TILE_M 128
#define TILE_N 64
#define GBK 32                         // floats per chunk (128B rows)
#define NCH (DMODEL / GBK)             // 32
#define NSTG 3
#define AREG_B (TILE_M * 128)          // 16384 bytes
#define BREG_B (TILE_N * 128)          //  8192 bytes
#define STG_BYTES (AREG_B + BREG_B)    // 24576
#define GEMM_SMEM (NSTG * STG_BYTES)   // 73728

__device__ __forceinline__ void cp16(uint32_t s, const void* g) {
    asm volatile("cp.async.cg.shared.global [%0], [%1], 16;\n" :: "r"(s), "l"(g));
}

__global__ __launch_bounds__(128) void gemm_tf32_nt(
    const float* __restrict__ A, const float* __restrict__ W,
    float* __restrict__ C, int Nn, int do_colsum)
{
    extern __shared__ char dsm[];
    const int tid = threadIdx.x;
    const int lane = tid & 31;
    const int w = tid >> 5;
    const int m0 = blockIdx.y * TILE_M;
    const int n0 = blockIdx.x * TILE_N;
    const int wm = (w >> 1) * 64;
    const int wn = (w & 1) * 32;

    const uint32_t sBase = (uint32_t)__cvta_generic_to_shared(dsm);

    const int a_row = wm + (lane & 7) + ((lane >> 3) & 1) * 8;
    const int a_c4 = (lane >> 4) & 1;
    const int b_row = wn + (lane & 7) + ((lane >> 4) & 1) * 8;
    const int b_c4 = (lane >> 3) & 1;

    float acc[4][4][4];
#pragma unroll
    for (int i = 0; i < 4; ++i)
#pragma unroll
        for (int j = 0; j < 4; ++j)
#pragma unroll
            for (int r = 0; r < 4; ++r) acc[i][j][r] = 0.0f;

    auto load_chunk = [&](int ck) {
        int stg = ck % NSTG;
        uint32_t sa = sBase + stg * STG_BYTES;
        uint32_t sb = sa + AREG_B;
        int k0 = ck * GBK;
#pragma unroll
        for (int j = 0; j < 8; ++j) {
            int c = tid + j * 128;
            int r = c >> 3;
            int ci = c & 7;
            cp16(sa + r * 128 + ((ci ^ (r & 7)) << 4),
                 A + (size_t)(m0 + r) * DMODEL + k0 + ci * 4);
        }
#pragma unroll
        for (int j = 0; j < 4; ++j) {
            int c = tid + j * 128;
            int r = c >> 3;
            int ci = c & 7;
            cp16(sb + r * 128 + ((ci ^ (r & 7)) << 4),
                 W + (size_t)(n0 + r) * DMODEL + k0 + ci * 4);
        }
        asm volatile("cp.async.commit_group;\n");
    };

    load_chunk(0);
    load_chunk(1);

    for (int it = 0; it < NCH; ++it) {
        if (it < NCH - 1) asm volatile("cp.async.wait_group 1;\n");
        else              asm volatile("cp.async.wait_group 0;\n");
        __syncthreads();
        if (it + 2 < NCH) load_chunk(it + 2);

        const uint32_t sa = sBase + (it % NSTG) * STG_BYTES;
        const uint32_t sb = sa + AREG_B;

        uint32_t af[2][4][4];
        uint32_t bf[2][4][2];

        auto ldfrag = [&](int buf, int ks) {
#pragma unroll
            for (int mi = 0; mi < 4; ++mi) {
                int r = a_row + mi * 16;
                int ci = ks * 2 + a_c4;
                uint32_t addr = sa + r * 128 + ((ci ^ (r & 7)) << 4);
                asm volatile(
                    "ldmatrix.sync.aligned.m8n8.x4.shared.b16 {%0,%1,%2,%3},[%4];\n"
                    : "=r"(af[buf][mi][0]), "=r"(af[buf][mi][1]),
                      "=r"(af[buf][mi][2]), "=r"(af[buf][mi][3])
                    : "r"(addr));
            }
#pragma unroll
            for (int np = 0; np < 2; ++np) {
                int r = b_row + np * 16;
                int ci = ks * 2 + b_c4;
                uint32_t addr = sb + r * 128 + ((ci ^ (r & 7)) << 4);
                uint32_t r0, r1, r2, r3;
                asm volatile(
                    "ldmatrix.sync.aligned.m8n8.x4.shared.b16 {%0,%1,%2,%3},[%4];\n"
                    : "=r"(r0), "=r"(r1), "=r"(r2), "=r"(r3) : "r"(addr));
                bf[buf][np * 2][0] = r0;     bf[buf][np * 2][1] = r1;
                bf[buf][np * 2 + 1][0] = r2; bf[buf][np * 2 + 1][1] = r3;
            }
        };

        ldfrag(0, 0);
#pragma unroll
        for (int ks = 0; ks < 4; ++ks) {
            if (ks < 3) ldfrag((ks + 1) & 1, ks + 1);
            const int cur = ks & 1;
#pragma unroll
            for (int mi = 0; mi < 4; ++mi)
#pragma unroll
                for (int ni = 0; ni < 4; ++ni) {
                    asm volatile(
                        "mma.sync.aligned.m16n8k8.row.col.f32.tf32.tf32.f32 "
                        "{%0,%1,%2,%3},{%4,%5,%6,%7},{%8,%9},{%0,%1,%2,%3};\n"
                        : "+f"(acc[mi][ni][0]), "+f"(acc[mi][ni][1]),
                          "+f"(acc[mi][ni][2]), "+f"(acc[mi][ni][3])
                        : "r"(af[cur][mi][0]), "r"(af[cur][mi][1]),
                          "r"(af[cur][mi][2]), "r"(af[cur][mi][3]),
                          "r"(bf[cur][ni][0]), "r"(bf[cur][ni][1]));
                }
        }
    }

    const int g = lane >> 2;
    const int cc = (lane & 3) * 2;
#pragma unroll
    for (int mi = 0; mi < 4; ++mi) {
#pragma unroll
        for (int ni = 0; ni < 4; ++ni) {
            int row = m0 + wm + mi * 16 + g;
            int col = n0 + wn + ni * 8 + cc;
            float v0 = acc[mi][ni][0], v1 = acc[mi][ni][1];
            float v2 = acc[mi][ni][2], v3 = acc[mi][ni][3];
            if (do_colsum) {   // HF path: pre-round for the tf32 fusion MMA
                v0 = tf32r(v0); v1 = tf32r(v1); v2 = tf32r(v2); v3 = tf32r(v3);
            }
            *(float2*)(C + (size_t)row * Nn + col) = make_float2(v0, v1);
            *(float2*)(C + (size_t)(row + 8) * Nn + col) = make_float2(v2, v3);
        }
    }

    if (do_colsum) {
        float cs[4][2];
#pragma unroll
        for (int ni = 0; ni < 4; ++ni) {
            float s0 = 0.0f, s1 = 0.0f;
#pragma unroll
            for (int mi = 0; mi < 4; ++mi) {
                s0 += acc[mi][ni][0] + acc[mi][ni][2];
                s1 += acc[mi][ni][1] + acc[mi][ni][3];
            }
            cs[ni][0] = s0;
            cs[ni][1] = s1;
        }
#pragma unroll
        for (int off = 4; off < 32; off <<= 1) {
#pragma unroll
            for (int ni = 0; ni < 4; ++ni) {
                cs[ni][0] += __shfl_xor_sync(0xffffffffu, cs[ni][0], off);
                cs[ni][1] += __shfl_xor_sync(0xffffffffu, cs[ni][1], off);
            }
        }
        if (lane < 4) {
            int slot = (m0 >> 7) * 2 + (wm >> 6);
#pragma unroll
            for (int ni = 0; ni < 4; ++ni) {
                g_cp[slot][n0 + wn + ni * 8 + lane * 2]     = cs[ni][0];
                g_cp[slot][n0 + wn + ni * 8 + lane * 2 + 1] = cs[ni][1];
            }
        }
    }
}

// ---------------------------------------------------------------------------
// Tensor-core fusion MLP. Per (128-token tile, head) block, 128 threads.
// Stage1: S = X(128x64) @ W1a^T (tf32 mma) + cvec -> exact GELU -> tf32 -> G
// Stage2: out = G @ W2^T + b2 -> tf32 -> g_multiT.
// X/G smem: 2 chunks x 16KB (128B rows, XOR swizzle). W: 2 chunks x 8KB.
// ---------------------------------------------------------------------------
#define FUS_X_OFF 0
#define FUS_W_OFF 32768
#define FUS_MN_OFF 49152
#define FUS_CV_OFF 49408
#define FUS_SMEM  49664

__device__ __forceinline__ float gelu_exact(float x) {
    return 0.5f * x * (1.0f + erff(x * 0.70710678118654752f));
}

__global__ __launch_bounds__(128) void fusion_tc(
    const float* __restrict__ fuW1, const float* __restrict__ fub1,
    const float* __restrict__ fub2)
{
    extern __shared__ char fsm[];
    const uint32_t sX = (uint32_t)__cvta_generic_to_shared(fsm) + FUS_X_OFF;
    const uint32_t sW = sX + (FUS_W_OFF - FUS_X_OFF);
    float* mnS = (float*)(fsm + FUS_MN_OFF);
    float* cvS = (float*)(fsm + FUS_CV_OFF);

    const int tid = threadIdx.x;
    const int lane = tid & 31;
    const int w = tid >> 5;
    const int m0 = blockIdx.x * 128;
    const int h = blockIdx.y;
    const int b = m0 >> 10;
    const int wm = (w >> 1) * 64;
    const int wn = (w & 1) * 32;

    const int a_row = wm + (lane & 7) + ((lane >> 3) & 1) * 8;
    const int a_c4 = (lane >> 4) & 1;
    const int b_row = wn + (lane & 7) + ((lane >> 4) & 1) * 8;
    const int b_c4 = (lane >> 3) & 1;

    // async loads: X (2048 16B chunks), W1a (1024 16B chunks)
#pragma unroll
    for (int j = 0; j < 16; ++j) {
        int c = tid + j * 128;
        int kc = c >> 10;
        int c2 = c & 1023;
        int r = c2 >> 3, ci = c2 & 7;
        cp16(sX + kc * 16384 + r * 128 + ((ci ^ (r & 7)) << 4),
             g_HF + (size_t)(m0 + r) * DMODEL + h * HD + kc * 32 + ci * 4);
    }
#pragma unroll
    for (int j = 0; j < 8; ++j) {
        int c = tid + j * 128;
        int kc = c >> 9;
        int c2 = c & 511;
        int r = c2 >> 3, ci = c2 & 7;
        cp16(sW + kc * 8192 + r * 128 + ((ci ^ (r & 7)) << 4),
             g_W1aT + (size_t)(h * HD + r) * HD + kc * 32 + ci * 4);
    }
    asm volatile("cp.async.commit_group;\n");

    // sequence mean (from gemm1's fused colsum partials)
    if (tid < HD) {
        int c = h * HD + tid;
        float s = 0.0f;
#pragma unroll
        for (int q = 0; q < 16; ++q)
            s += g_cp[b * 16 + q][c];
        mnS[tid] = s * (1.0f / 1024.0f);
    }
    __syncthreads();   // mnS visible

    // inline cvec: 2 threads per j-row (fp32, from global fuW1 mid segment)
    {
        const int j = tid >> 1;
        const int t = tid & 1;
        const float* wrow = fuW1 + (size_t)(h * HD + j) * (3 * HD);
        float cacc = 0.0f;
#pragma unroll
        for (int q = 0; q < 8; ++q) {
            int e = t * 32 + q * 4;
            float4 wa = *(const float4*)(wrow + 64 + e);
            float4 wb = *(const float4*)(wrow + 128 + e);
            cacc = fmaf(wa.x + wb.x, mnS[e + 0], cacc);
            cacc = fmaf(wa.y + wb.y, mnS[e + 1], cacc);
            cacc = fmaf(wa.z + wb.z, mnS[e + 2], cacc);
            cacc = fmaf(wa.w + wb.w, mnS[e + 3], cacc);
        }
        cacc += __shfl_down_sync(0xffffffffu, cacc, 1, 2);
        if (t == 0) cvS[j] = cacc + fub1[h * HD + j];
    }

    asm volatile("cp.async.wait_group 0;\n");
    __syncthreads();

    uint32_t af[2][4][4];
    uint32_t bf[2][4][2];

    auto ldfrag = [&](uint32_t sa, uint32_t sb, int buf, int ks) {
#pragma unroll
        for (int mi = 0; mi < 4; ++mi) {
            int r = a_row + mi * 16;
            int ci = ks * 2 + a_c4;
            uint32_t addr = sa + r * 128 + ((ci ^ (r & 7)) << 4);
            asm volatile(
                "ldmatrix.sync.aligned.m8n8.x4.shared.b16 {%0,%1,%2,%3},[%4];\n"
                : "=r"(af[buf][mi][0]), "=r"(af[buf][mi][1]),
                  "=r"(af[buf][mi][2]), "=r"(af[buf][mi][3])
                : "r"(addr));
        }
#pragma unroll
        for (int np = 0; np < 2; ++np) {
            int r = b_row + np * 16;
            int ci = ks * 2 + b_c4;
            uint32_t addr = sb + r * 128 + ((ci ^ (r & 7)) << 4);
            uint32_t r0, r1, r2, r3;
            asm volatile(
                "ldmatrix.sync.aligned.m8n8.x4.shared.b16 {%0,%1,%2,%3},[%4];\n"
                : "=r"(r0), "=r"(r1), "=r"(r2), "=r"(r3) : "r"(addr));
            bf[buf][np * 2][0] = r0;     bf[buf][np * 2][1] = r1;
            bf[buf][np * 2 + 1][0] = r2; bf[buf][np * 2 + 1][1] = r3;
        }
    };

    auto mma_stage = [&](float (&ACC)[4][4][4]) {
#pragma unroll
        for (int kc = 0; kc < 2; ++kc) {
            const uint32_t sa = sX + kc * 16384;
            const uint32_t sb = sW + kc * 8192;
            ldfrag(sa, sb, 0, 0);
#pragma unroll
            for (int ks = 0; ks < 4; ++ks) {
                if (ks < 3) ldfrag(sa, sb, (ks + 1) & 1, ks + 1);
                const int cur = ks & 1;
#pragma unroll
                for (int mi = 0; mi < 4; ++mi)
#pragma unroll
                    for (int ni = 0; ni < 4; ++ni) {
                        asm volatile(
                            "mma.sync.aligned.m16n8k8.row.col.f32.tf32.tf32.f32 "
                            "{%0,%1,%2,%3},{%4,%5,%6,%7},{%8,%9},{%0,%1,%2,%3};\n"
                            : "+f"(ACC[mi][ni][0]), "+f"(ACC[mi][ni][1]),
                              "+f"(ACC[mi][ni][2]), "+f"(ACC[mi][ni][3])
                            : "r"(af[cur][mi][0]), "r"(af[cur][mi][1]),
                              "r"(af[cur][mi][2]), "r"(af[cur][mi][3]),
                              "r"(bf[cur][ni][0]), "r"(bf[cur][ni][1]));
                    }
            }
        }
    };

    float acc[4][4][4];
#pragma unroll
    for (int i = 0; i < 4; ++i)
#pragma unroll
        for (int j = 0; j < 4; ++j)
#pragma unroll
            for (int r = 0; r < 4; ++r) acc[i][j][r] = 0.0f;

    mma_stage(acc);
    __syncthreads();   // all ldmatrix reads of X/W1 done

    // issue W2 cp.async FIRST (overlaps with GELU math below; sW reads done)
#pragma unroll
    for (int j = 0; j < 8; ++j) {
        int c = tid + j * 128;
        int kc = c >> 9;
        int c2 = c & 511;
        int r = c2 >> 3, ci = c2 & 7;
        cp16(sW + kc * 8192 + r * 128 + ((ci ^ (r & 7)) << 4),
             g_W2T + (size_t)(h * HD + r) * HD + kc * 32 + ci * 4);
    }
    asm volatile("cp.async.commit_group;\n");

    // GELU(+cv) -> tf32 -> G (overwrites X buffer)
    const int g = lane >> 2;
    const int cc = (lane & 3) * 2;
#pragma unroll
    for (int mi = 0; mi < 4; ++mi) {
#pragma unroll
        for (int ni = 0; ni < 4; ++ni) {
            int j0 = wn + ni * 8 + cc;
            float cv0 = cvS[j0], cv1 = cvS[j0 + 1];
            float x0 = tf32r(gelu_exact(acc[mi][ni][0] + cv0));
            float x1 = tf32r(gelu_exact(acc[mi][ni][1] + cv1));
            float x2 = tf32r(gelu_exact(acc[mi][ni][2] + cv0));
            float x3 = tf32r(gelu_exact(acc[mi][ni][3] + cv1));
            int kc = j0 >> 5;
            int cl = j0 & 31;
            int ci = cl >> 2;
            int r0 = wm + mi * 16 + g;
            int r1 = r0 + 8;
            uint32_t ad0 = sX + kc * 16384 + r0 * 128 +
                           ((ci ^ (r0 & 7)) << 4) + (cl & 3) * 4;
            uint32_t ad1 = sX + kc * 16384 + r1 * 128 +
                           ((ci ^ (r1 & 7)) << 4) + (cl & 3) * 4;
            asm volatile("st.shared.v2.f32 [%0], {%1,%2};"
                         :: "r"(ad0), "f"(x0), "f"(x1) : "memory");
            asm volatile("st.shared.v2.f32 [%0], {%1,%2};"
                         :: "r"(ad1), "f"(x2), "f"(x3) : "memory");
        }
    }
    asm volatile("cp.async.wait_group 0;\n");
    __syncthreads();   // G + W2 visible

    float acc2[4][4][4];
#pragma unroll
    for (int i = 0; i < 4; ++i)
#pragma unroll
        for (int j = 0; j < 4; ++j)
#pragma unroll
            for (int r = 0; r < 4; ++r) acc2[i][j][r] = 0.0f;

    mma_stage(acc2);

    // epilogue: +b2, tf32 round, store multi
#pragma unroll
    for (int mi = 0; mi < 4; ++mi) {
#pragma unroll
        for (int ni = 0; ni < 4; ++ni) {
            int f0 = wn + ni * 8 + cc;
            float b0 = fub2[h * HD + f0];
            float b1 = fub2[h * HD + f0 + 1];
            int row = m0 + wm + mi * 16 + g;
            size_t base = (size_t)row * DMODEL + h * HD + f0;
            *(float2*)&g_multiT[base] =
                make_float2(tf32r(acc2[mi][ni][0] + b0),
                            tf32r(acc2[mi][ni][1] + b1));
            *(float2*)&g_multiT[base + 8 * DMODEL] =
                make_float2(tf32r(acc2[mi][ni][2] + b0),
                            tf32r(acc2[mi][ni][3] + b1));
        }
    }
}

// ---------------------------------------------------------------------------
// Trivial outputs: fwd/bwd targets + avg_strength (analytic constants)
// ---------------------------------------------------------------------------
__global__ void extras_kernel(const int* __restrict__ prev,
                              const float* __restrict__ cr,
                              float* __restrict__ out)
{
    int idx = blockIdx.x * blockDim.x + threadIdx.x;
    if (idx >= NTOK) return;
    int n = idx & (NSEQ - 1);

    float thr = floorf((float)NSEQ / (1.0f + expf(-cr[0])));
    float fwd = 511.0f;
    if ((float)n >= thr) {
        int p = prev[idx];
        p = p < 0 ? 0 : (p > NSEQ - 1 ? NSEQ - 1 : p);
        fwd = (float)p;
    }
    out[OFF_FWD + idx] = fwd;
    out[OFF_BWD + idx] = 511.0f;
    out[OFF_STR + idx] = 1.0f - logf(1.0f / (float)NSEQ + 1e-8f);
}

// ---------------------------------------------------------------------------
extern "C" void kernel_launch(void* const* d_in, const int* in_sizes, int n_in,
                              void* d_out, int out_size)
{
    const float* h    = (const float*)d_in[0];
    const int*   prev = (const int*)d_in[1];
    // d_in[2..9]: forward/backward encoder weights — provably dead code
    const float* Wv   = (const float*)d_in[10];
    const float* fuW1 = (const float*)d_in[11];
    const float* fub1 = (const float*)d_in[12];
    const float* fuW2 = (const float*)d_in[13];
    const float* fub2 = (const float*)d_in[14];
    const float* Wo   = (const float*)d_in[15];
    const float* cr   = (const float*)d_in[16];
    float* out = (float*)d_out;

    float *pHF = nullptr, *phT = nullptr, *pWvT = nullptr, *pWoT = nullptr,
          *pMT = nullptr;
    cudaGetSymbolAddress((void**)&pHF, g_HF);
    cudaGetSymbolAddress((void**)&phT, g_hT);
    cudaGetSymbolAddress((void**)&pWvT, g_WvT);
    cudaGetSymbolAddress((void**)&pWoT, g_WoT);
    cudaGetSymbolAddress((void**)&pMT, g_multiT);

    cudaFuncSetAttribute(gemm_tf32_nt,
                         cudaFuncAttributeMaxDynamicSharedMemorySize, GEMM_SMEM);
    cudaFuncSetAttribute(fusion_tc,
                         cudaFuncAttributeMaxDynamicSharedMemorySize, FUS_SMEM);

    // 0) tf32-RN converts in one launch (h, Wv, Wo, W1a, W2)
    tf32_all<<<4224, 256>>>(h, Wv, Wo, fuW1, fuW2);

    dim3 g1(DMODEL / TILE_N, NTOK / TILE_M);   // (16, 16) = 256 CTAs

    // 1) head_features = h @ Wv^T  (tf32 mma) + colsums; HF stored tf32-rounded
    gemm_tf32_nt<<<g1, 128, GEMM_SMEM>>>(phT, pWvT, pHF, DMODEL, 1);

    // 2) tensor-core fusion MLP -> g_multiT
    fusion_tc<<<dim3(NTOK / 128, NH), 128, FUS_SMEM>>>(fuW1, fub1, fub2);

    // 3) final_output = multi @ Wo^T
    gemm_tf32_nt<<<g1, 128, GEMM_SMEM>>>(pMT, pWoT, out, DMODEL, 0);

    // 4) analytic outputs
    extras_kernel<<<(NTOK + 255) / 256, 256>>>(prev, cr, out);
}